// round 8
// baseline (speedup 1.0000x reference)
#include <cuda_runtime.h>
#include <math.h>

#define D 1024
#define S 128
#define DECAY 0.99f
#define INHIB 1.5f
#define TOPK 51
#define SCAN_R 4

// Scratch (static device globals — no allocation).
__device__ float g_sbuf[S * D];    // sparsified token vectors [S][D]
__device__ float g_expect[S * D];  // expectation_t[j] accumulated by scan atomics

// ---------------------------------------------------------------------------
// Kernel 1: sparsify. 128 blocks x 64 threads (one radix warp per SM).
// Warp 0: exact 1-bit radix top-k select for token bid (nonneg-float order
// == uint order) with EARLY EXIT: the output mask is (pos >= thr), and any
// thr inside the (52nd, 51st]-value gap yields the identical mask, so we can
// stop as soon as count == TOPK exactly. Tie cases never produce count==TOPK
// at the boundary and fall through to full bit resolution (== reference).
// Warp 1: zero g_expect row bid.
// ---------------------------------------------------------------------------
__global__ void __launch_bounds__(64) sparsify_kernel(const float* __restrict__ emb) {
    const int t = blockIdx.x;
    const int lane = threadIdx.x & 31;

    if (threadIdx.x >= 32) {  // warp 1: zero g_expect row t
        float4 z = make_float4(0.f, 0.f, 0.f, 0.f);
        float4* e4 = reinterpret_cast<float4*>(g_expect + (size_t)t * D);
#pragma unroll
        for (int c = 0; c < 8; ++c) e4[c * 32 + lane] = z;
        cudaTriggerProgrammaticLaunchCompletion();
        return;
    }

    // warp 0: load relu(x) as raw bits, 32 values per lane, coalesced
    unsigned pb[32];
    const float4* row = reinterpret_cast<const float4*>(emb + (size_t)t * D);
#pragma unroll
    for (int c = 0; c < 8; ++c) {
        float4 x = row[c * 32 + lane];
        pb[c * 4 + 0] = __float_as_uint(fmaxf(x.x, 0.f));
        pb[c * 4 + 1] = __float_as_uint(fmaxf(x.y, 0.f));
        pb[c * 4 + 2] = __float_as_uint(fmaxf(x.z, 0.f));
        pb[c * 4 + 3] = __float_as_uint(fmaxf(x.w, 0.f));
    }

    // 1-bit radix: max T with count(bits >= T) >= TOPK, early-exit on ==.
    unsigned thr = 0u;
#pragma unroll 1
    for (int b = 30; b >= 0; --b) {
        const unsigned cand = thr | (1u << b);
        int c = 0;
#pragma unroll
        for (int k = 0; k < 32; ++k) c += (pb[k] >= cand) ? 1 : 0;
        c = __reduce_add_sync(0xffffffffu, c);
        if (c >= TOPK) {
            thr = cand;
            if (c == TOPK) break;  // mask already exact
        }
    }

    float4* outp = reinterpret_cast<float4*>(g_sbuf + (size_t)t * D);
#pragma unroll
    for (int c = 0; c < 8; ++c) {
        float4 sv;
        sv.x = (pb[c * 4 + 0] >= thr) ? __uint_as_float(pb[c * 4 + 0]) : 0.f;
        sv.y = (pb[c * 4 + 1] >= thr) ? __uint_as_float(pb[c * 4 + 1]) : 0.f;
        sv.z = (pb[c * 4 + 2] >= thr) ? __uint_as_float(pb[c * 4 + 2]) : 0.f;
        sv.w = (pb[c * 4 + 3] >= thr) ? __uint_as_float(pb[c * 4 + 3]) : 0.f;
        outp[c * 32 + lane] = sv;
    }
    cudaTriggerProgrammaticLaunchCompletion();
}

// ---------------------------------------------------------------------------
// Kernel 2: the scan with fused expectation accumulation (proven engine).
//     v <- relu(DECAY*v + s_t[i]*s_t[j]*g_t),   g_t = 1 - c_t*INHIB
// Thread owns 4 rows x 4 cols; v register-resident across all 128 steps;
// snapshots stream out with __stcs. s_{t+1}[i]*v -> g_expect[t+1] atomics
// (block-uniform skip when all 4 s-rows are zero, ~81% of steps).
// PDL: g_sh (input-only) is staged BEFORE the grid-dependency sync.
// ---------------------------------------------------------------------------
__global__ void __launch_bounds__(256) scan_kernel(const float* __restrict__ con,
                                                  float* __restrict__ states) {
    const int tid = threadIdx.x;
    const int i0 = blockIdx.x * SCAN_R;
    const int j = tid * 4;

    __shared__ float4 si_sh[S];  // s_t[i0..i0+3] for all t
    __shared__ float g_sh[S];

    // Pre-sync work: depends only on kernel inputs, not on sparsify.
    if (tid < S) g_sh[tid] = 1.0f - con[tid] * INHIB;

    cudaGridDependencySynchronize();  // PDL: wait for sparsify completion

    if (tid < S)
        si_sh[tid] = *reinterpret_cast<const float4*>(g_sbuf + (size_t)tid * D + i0);
    __syncthreads();

    float4 v[SCAN_R];
#pragma unroll
    for (int r = 0; r < SCAN_R; ++r) v[r] = make_float4(0.f, 0.f, 0.f, 0.f);

    float4 sj = __ldg(reinterpret_cast<const float4*>(g_sbuf + j));  // s_t[j..j+3]
    for (int t = 0; t < S; ++t) {
        float4 sjn = sj;
        if (t + 1 < S)
            sjn = __ldg(reinterpret_cast<const float4*>(g_sbuf + (size_t)(t + 1) * D + j));
        const float g = g_sh[t];
        const float4 si = si_sh[t];
        const float a0 = si.x * g, a1 = si.y * g, a2 = si.z * g, a3 = si.w * g;
        float* o = states + (size_t)t * D * D + j;

        v[0].x = fmaxf(fmaf(a0, sj.x, DECAY * v[0].x), 0.f);
        v[0].y = fmaxf(fmaf(a0, sj.y, DECAY * v[0].y), 0.f);
        v[0].z = fmaxf(fmaf(a0, sj.z, DECAY * v[0].z), 0.f);
        v[0].w = fmaxf(fmaf(a0, sj.w, DECAY * v[0].w), 0.f);
        v[1].x = fmaxf(fmaf(a1, sj.x, DECAY * v[1].x), 0.f);
        v[1].y = fmaxf(fmaf(a1, sj.y, DECAY * v[1].y), 0.f);
        v[1].z = fmaxf(fmaf(a1, sj.z, DECAY * v[1].z), 0.f);
        v[1].w = fmaxf(fmaf(a1, sj.w, DECAY * v[1].w), 0.f);
        v[2].x = fmaxf(fmaf(a2, sj.x, DECAY * v[2].x), 0.f);
        v[2].y = fmaxf(fmaf(a2, sj.y, DECAY * v[2].y), 0.f);
        v[2].z = fmaxf(fmaf(a2, sj.z, DECAY * v[2].z), 0.f);
        v[2].w = fmaxf(fmaf(a2, sj.w, DECAY * v[2].w), 0.f);
        v[3].x = fmaxf(fmaf(a3, sj.x, DECAY * v[3].x), 0.f);
        v[3].y = fmaxf(fmaf(a3, sj.y, DECAY * v[3].y), 0.f);
        v[3].z = fmaxf(fmaf(a3, sj.z, DECAY * v[3].z), 0.f);
        v[3].w = fmaxf(fmaf(a3, sj.w, DECAY * v[3].w), 0.f);

        __stcs(reinterpret_cast<float4*>(o + (size_t)(i0 + 0) * D), v[0]);
        __stcs(reinterpret_cast<float4*>(o + (size_t)(i0 + 1) * D), v[1]);
        __stcs(reinterpret_cast<float4*>(o + (size_t)(i0 + 2) * D), v[2]);
        __stcs(reinterpret_cast<float4*>(o + (size_t)(i0 + 3) * D), v[3]);

        if (t + 1 < S) {
            const float4 sn = si_sh[t + 1];  // block-uniform
            if (sn.x != 0.f || sn.y != 0.f || sn.z != 0.f || sn.w != 0.f) {
                float4 cacc;
                cacc.x = sn.x * v[0].x + sn.y * v[1].x + sn.z * v[2].x + sn.w * v[3].x;
                cacc.y = sn.x * v[0].y + sn.y * v[1].y + sn.z * v[2].y + sn.w * v[3].y;
                cacc.z = sn.x * v[0].z + sn.y * v[1].z + sn.z * v[2].z + sn.w * v[3].z;
                cacc.w = sn.x * v[0].w + sn.y * v[1].w + sn.z * v[2].w + sn.w * v[3].w;
                float* e = g_expect + (size_t)(t + 1) * D + j;
                atomicAdd(e + 0, cacc.x);
                atomicAdd(e + 1, cacc.y);
                atomicAdd(e + 2, cacc.z);
                atomicAdd(e + 3, cacc.w);
            }
        }
        sj = sjn;
    }
}

// ---------------------------------------------------------------------------
// Kernel 3: finalize. drift_t = ||s_t - expect_t|| (expect_0 = 0 => ||s_0||).
// PDL: s4 (ready since sparsify) loads BEFORE the grid-dependency sync,
// hiding its DRAM latency behind the scan drain.
// ---------------------------------------------------------------------------
__global__ void __launch_bounds__(256) finalize_kernel(float* __restrict__ drifts) {
    const int t = blockIdx.x;
    const int tid = threadIdx.x;
    const int lane = tid & 31, wid = tid >> 5;

    float4 s4 = reinterpret_cast<const float4*>(g_sbuf + (size_t)t * D)[tid];

    cudaGridDependencySynchronize();  // PDL: wait for scan completion

    float4 e4 = reinterpret_cast<const float4*>(g_expect + (size_t)t * D)[tid];
    const float dx = s4.x - e4.x, dy = s4.y - e4.y;
    const float dz = s4.z - e4.z, dw = s4.w - e4.w;
    float sum = dx * dx + dy * dy + dz * dz + dw * dw;
#pragma unroll
    for (int o = 16; o > 0; o >>= 1) sum += __shfl_xor_sync(0xffffffffu, sum, o);

    __shared__ float ws[8];
    if (lane == 0) ws[wid] = sum;
    __syncthreads();
    if (tid == 0) {
        float tot = 0.f;
        for (int w = 0; w < 8; ++w) tot += ws[w];
        drifts[t] = sqrtf(tot);
    }
}

// ---------------------------------------------------------------------------
extern "C" void kernel_launch(void* const* d_in, const int* in_sizes, int n_in,
                              void* d_out, int out_size) {
    const float* emb;
    const float* con;
    if (in_sizes[0] == S) {
        con = (const float*)d_in[0];
        emb = (const float*)d_in[1];
    } else {
        emb = (const float*)d_in[0];
        con = (const float*)d_in[1];
    }
    float* out = (float*)d_out;
    float* drifts = out;      // [S]
    float* states = out + S;  // [S, D, D]

    sparsify_kernel<<<S, 64>>>(emb);

    cudaLaunchAttribute attr[1];
    attr[0].id = cudaLaunchAttributeProgrammaticStreamSerialization;
    attr[0].val.programmaticStreamSerializationAllowed = 1;

    {
        cudaLaunchConfig_t cfg = {};
        cfg.gridDim = dim3(D / SCAN_R);
        cfg.blockDim = dim3(256);
        cfg.dynamicSmemBytes = 0;
        cfg.stream = (cudaStream_t)0;
        cfg.attrs = attr;
        cfg.numAttrs = 1;
        cudaLaunchKernelEx(&cfg, scan_kernel, con, states);
    }
    {
        cudaLaunchConfig_t cfg = {};
        cfg.gridDim = dim3(S);
        cfg.blockDim = dim3(256);
        cfg.dynamicSmemBytes = 0;
        cfg.stream = (cudaStream_t)0;
        cfg.attrs = attr;
        cfg.numAttrs = 1;
        cudaLaunchKernelEx(&cfg, finalize_kernel, drifts);
    }
}

// round 9
// speedup vs baseline: 1.0006x; 1.0006x over previous
#include <cuda_runtime.h>
#include <math.h>

#define D 1024
#define S 128
#define DECAY 0.99f
#define INHIB 1.5f
#define TOPK 51
#define SCAN_R 4

// Scratch (static device globals — no allocation).
__device__ float g_sbuf[S * D];    // sparsified token vectors [S][D]
__device__ float g_expect[S * D];  // expectation_t[j] accumulated by scan atomics

// ---------------------------------------------------------------------------
// Kernel 1: sparsify. 128 blocks x 64 threads (one radix warp per SM).
// Warp 0: exact 1-bit radix top-k select for token bid (nonneg-float order
// == uint order) with EARLY EXIT: the output mask is (pos >= thr), and any
// thr inside the (52nd, 51st]-value gap yields the identical mask, so we can
// stop as soon as count == TOPK exactly. Tie cases never produce count==TOPK
// at the boundary and fall through to full bit resolution (== reference).
// Warp 1: zero g_expect row bid.
// ---------------------------------------------------------------------------
__global__ void __launch_bounds__(64) sparsify_kernel(const float* __restrict__ emb) {
    const int t = blockIdx.x;
    const int lane = threadIdx.x & 31;

    if (threadIdx.x >= 32) {  // warp 1: zero g_expect row t
        float4 z = make_float4(0.f, 0.f, 0.f, 0.f);
        float4* e4 = reinterpret_cast<float4*>(g_expect + (size_t)t * D);
#pragma unroll
        for (int c = 0; c < 8; ++c) e4[c * 32 + lane] = z;
        cudaTriggerProgrammaticLaunchCompletion();
        return;
    }

    // warp 0: load relu(x) as raw bits, 32 values per lane, coalesced
    unsigned pb[32];
    const float4* row = reinterpret_cast<const float4*>(emb + (size_t)t * D);
#pragma unroll
    for (int c = 0; c < 8; ++c) {
        float4 x = row[c * 32 + lane];
        pb[c * 4 + 0] = __float_as_uint(fmaxf(x.x, 0.f));
        pb[c * 4 + 1] = __float_as_uint(fmaxf(x.y, 0.f));
        pb[c * 4 + 2] = __float_as_uint(fmaxf(x.z, 0.f));
        pb[c * 4 + 3] = __float_as_uint(fmaxf(x.w, 0.f));
    }

    // 1-bit radix: max T with count(bits >= T) >= TOPK, early-exit on ==.
    unsigned thr = 0u;
#pragma unroll 1
    for (int b = 30; b >= 0; --b) {
        const unsigned cand = thr | (1u << b);
        int c = 0;
#pragma unroll
        for (int k = 0; k < 32; ++k) c += (pb[k] >= cand) ? 1 : 0;
        c = __reduce_add_sync(0xffffffffu, c);
        if (c >= TOPK) {
            thr = cand;
            if (c == TOPK) break;  // mask already exact
        }
    }

    float4* outp = reinterpret_cast<float4*>(g_sbuf + (size_t)t * D);
#pragma unroll
    for (int c = 0; c < 8; ++c) {
        float4 sv;
        sv.x = (pb[c * 4 + 0] >= thr) ? __uint_as_float(pb[c * 4 + 0]) : 0.f;
        sv.y = (pb[c * 4 + 1] >= thr) ? __uint_as_float(pb[c * 4 + 1]) : 0.f;
        sv.z = (pb[c * 4 + 2] >= thr) ? __uint_as_float(pb[c * 4 + 2]) : 0.f;
        sv.w = (pb[c * 4 + 3] >= thr) ? __uint_as_float(pb[c * 4 + 3]) : 0.f;
        outp[c * 32 + lane] = sv;
    }
    cudaTriggerProgrammaticLaunchCompletion();
}

// ---------------------------------------------------------------------------
// Kernel 2: the scan with fused expectation accumulation (proven engine).
//     v <- relu(DECAY*v + s_t[i]*s_t[j]*g_t),   g_t = 1 - c_t*INHIB
// Thread owns 4 rows x 4 cols; v register-resident across all 128 steps;
// snapshots stream out with __stcs. s_{t+1}[i]*v -> g_expect[t+1] atomics
// (block-uniform skip when all 4 s-rows are zero, ~81% of steps).
// PDL: g_sh (input-only) is staged BEFORE the grid-dependency sync.
// ---------------------------------------------------------------------------
__global__ void __launch_bounds__(256) scan_kernel(const float* __restrict__ con,
                                                  float* __restrict__ states) {
    const int tid = threadIdx.x;
    const int i0 = blockIdx.x * SCAN_R;
    const int j = tid * 4;

    __shared__ float4 si_sh[S];  // s_t[i0..i0+3] for all t
    __shared__ float g_sh[S];

    // Pre-sync work: depends only on kernel inputs, not on sparsify.
    if (tid < S) g_sh[tid] = 1.0f - con[tid] * INHIB;

    cudaGridDependencySynchronize();  // PDL: wait for sparsify completion

    if (tid < S)
        si_sh[tid] = *reinterpret_cast<const float4*>(g_sbuf + (size_t)tid * D + i0);
    __syncthreads();

    float4 v[SCAN_R];
#pragma unroll
    for (int r = 0; r < SCAN_R; ++r) v[r] = make_float4(0.f, 0.f, 0.f, 0.f);

    float4 sj = __ldg(reinterpret_cast<const float4*>(g_sbuf + j));  // s_t[j..j+3]
    for (int t = 0; t < S; ++t) {
        float4 sjn = sj;
        if (t + 1 < S)
            sjn = __ldg(reinterpret_cast<const float4*>(g_sbuf + (size_t)(t + 1) * D + j));
        const float g = g_sh[t];
        const float4 si = si_sh[t];
        const float a0 = si.x * g, a1 = si.y * g, a2 = si.z * g, a3 = si.w * g;
        float* o = states + (size_t)t * D * D + j;

        v[0].x = fmaxf(fmaf(a0, sj.x, DECAY * v[0].x), 0.f);
        v[0].y = fmaxf(fmaf(a0, sj.y, DECAY * v[0].y), 0.f);
        v[0].z = fmaxf(fmaf(a0, sj.z, DECAY * v[0].z), 0.f);
        v[0].w = fmaxf(fmaf(a0, sj.w, DECAY * v[0].w), 0.f);
        v[1].x = fmaxf(fmaf(a1, sj.x, DECAY * v[1].x), 0.f);
        v[1].y = fmaxf(fmaf(a1, sj.y, DECAY * v[1].y), 0.f);
        v[1].z = fmaxf(fmaf(a1, sj.z, DECAY * v[1].z), 0.f);
        v[1].w = fmaxf(fmaf(a1, sj.w, DECAY * v[1].w), 0.f);
        v[2].x = fmaxf(fmaf(a2, sj.x, DECAY * v[2].x), 0.f);
        v[2].y = fmaxf(fmaf(a2, sj.y, DECAY * v[2].y), 0.f);
        v[2].z = fmaxf(fmaf(a2, sj.z, DECAY * v[2].z), 0.f);
        v[2].w = fmaxf(fmaf(a2, sj.w, DECAY * v[2].w), 0.f);
        v[3].x = fmaxf(fmaf(a3, sj.x, DECAY * v[3].x), 0.f);
        v[3].y = fmaxf(fmaf(a3, sj.y, DECAY * v[3].y), 0.f);
        v[3].z = fmaxf(fmaf(a3, sj.z, DECAY * v[3].z), 0.f);
        v[3].w = fmaxf(fmaf(a3, sj.w, DECAY * v[3].w), 0.f);

        __stcs(reinterpret_cast<float4*>(o + (size_t)(i0 + 0) * D), v[0]);
        __stcs(reinterpret_cast<float4*>(o + (size_t)(i0 + 1) * D), v[1]);
        __stcs(reinterpret_cast<float4*>(o + (size_t)(i0 + 2) * D), v[2]);
        __stcs(reinterpret_cast<float4*>(o + (size_t)(i0 + 3) * D), v[3]);

        if (t + 1 < S) {
            const float4 sn = si_sh[t + 1];  // block-uniform
            if (sn.x != 0.f || sn.y != 0.f || sn.z != 0.f || sn.w != 0.f) {
                float4 cacc;
                cacc.x = sn.x * v[0].x + sn.y * v[1].x + sn.z * v[2].x + sn.w * v[3].x;
                cacc.y = sn.x * v[0].y + sn.y * v[1].y + sn.z * v[2].y + sn.w * v[3].y;
                cacc.z = sn.x * v[0].z + sn.y * v[1].z + sn.z * v[2].z + sn.w * v[3].z;
                cacc.w = sn.x * v[0].w + sn.y * v[1].w + sn.z * v[2].w + sn.w * v[3].w;
                float* e = g_expect + (size_t)(t + 1) * D + j;
                atomicAdd(e + 0, cacc.x);
                atomicAdd(e + 1, cacc.y);
                atomicAdd(e + 2, cacc.z);
                atomicAdd(e + 3, cacc.w);
            }
        }
        sj = sjn;
    }
}

// ---------------------------------------------------------------------------
// Kernel 3: finalize. drift_t = ||s_t - expect_t|| (expect_0 = 0 => ||s_0||).
// PDL: s4 (ready since sparsify) loads BEFORE the grid-dependency sync,
// hiding its DRAM latency behind the scan drain.
// ---------------------------------------------------------------------------
__global__ void __launch_bounds__(256) finalize_kernel(float* __restrict__ drifts) {
    const int t = blockIdx.x;
    const int tid = threadIdx.x;
    const int lane = tid & 31, wid = tid >> 5;

    float4 s4 = reinterpret_cast<const float4*>(g_sbuf + (size_t)t * D)[tid];

    cudaGridDependencySynchronize();  // PDL: wait for scan completion

    float4 e4 = reinterpret_cast<const float4*>(g_expect + (size_t)t * D)[tid];
    const float dx = s4.x - e4.x, dy = s4.y - e4.y;
    const float dz = s4.z - e4.z, dw = s4.w - e4.w;
    float sum = dx * dx + dy * dy + dz * dz + dw * dw;
#pragma unroll
    for (int o = 16; o > 0; o >>= 1) sum += __shfl_xor_sync(0xffffffffu, sum, o);

    __shared__ float ws[8];
    if (lane == 0) ws[wid] = sum;
    __syncthreads();
    if (tid == 0) {
        float tot = 0.f;
        for (int w = 0; w < 8; ++w) tot += ws[w];
        drifts[t] = sqrtf(tot);
    }
}

// ---------------------------------------------------------------------------
extern "C" void kernel_launch(void* const* d_in, const int* in_sizes, int n_in,
                              void* d_out, int out_size) {
    const float* emb;
    const float* con;
    if (in_sizes[0] == S) {
        con = (const float*)d_in[0];
        emb = (const float*)d_in[1];
    } else {
        emb = (const float*)d_in[0];
        con = (const float*)d_in[1];
    }
    float* out = (float*)d_out;
    float* drifts = out;      // [S]
    float* states = out + S;  // [S, D, D]

    sparsify_kernel<<<S, 64>>>(emb);

    cudaLaunchAttribute attr[1];
    attr[0].id = cudaLaunchAttributeProgrammaticStreamSerialization;
    attr[0].val.programmaticStreamSerializationAllowed = 1;

    {
        cudaLaunchConfig_t cfg = {};
        cfg.gridDim = dim3(D / SCAN_R);
        cfg.blockDim = dim3(256);
        cfg.dynamicSmemBytes = 0;
        cfg.stream = (cudaStream_t)0;
        cfg.attrs = attr;
        cfg.numAttrs = 1;
        cudaLaunchKernelEx(&cfg, scan_kernel, con, states);
    }
    {
        cudaLaunchConfig_t cfg = {};
        cfg.gridDim = dim3(S);
        cfg.blockDim = dim3(256);
        cfg.dynamicSmemBytes = 0;
        cfg.stream = (cudaStream_t)0;
        cfg.attrs = attr;
        cfg.numAttrs = 1;
        cudaLaunchKernelEx(&cfg, finalize_kernel, drifts);
    }
}

// round 10
// speedup vs baseline: 1.1462x; 1.1455x over previous
#include <cuda_runtime.h>
#include <math.h>

#define D 1024
#define S 128
#define DECAY 0.99f
#define INHIB 1.5f
#define TOPK 51
#define SCAN_R 4

// Scratch (static device globals — no allocation).
__device__ float g_sbuf[S * D];    // sparsified token vectors [S][D]
__device__ float g_expect[S * D];  // expectation_t[j] accumulated by scan reds

// Vector float4 global reduction (sm_90+): one REDG instead of four.
__device__ __forceinline__ void red_add_v4(float* p, float4 v) {
    asm volatile("red.global.add.v4.f32 [%0], {%1, %2, %3, %4};"
                 :: "l"(p), "f"(v.x), "f"(v.y), "f"(v.z), "f"(v.w)
                 : "memory");
}

// ---------------------------------------------------------------------------
// Kernel 1: sparsify. 128 blocks x 64 threads (one radix warp per SM).
// Warp 0: exact 1-bit radix top-k select for token bid (nonneg-float order
// == uint order) with early exit: the output mask is (pos >= thr), and any
// thr inside the (52nd, 51st]-value gap yields the identical mask, so we stop
// as soon as count == TOPK exactly. Tie cases fall through to full resolution.
// Warp 1: zero g_expect row bid.
// ---------------------------------------------------------------------------
__global__ void __launch_bounds__(64) sparsify_kernel(const float* __restrict__ emb) {
    const int t = blockIdx.x;
    const int lane = threadIdx.x & 31;

    if (threadIdx.x >= 32) {  // warp 1: zero g_expect row t
        float4 z = make_float4(0.f, 0.f, 0.f, 0.f);
        float4* e4 = reinterpret_cast<float4*>(g_expect + (size_t)t * D);
#pragma unroll
        for (int c = 0; c < 8; ++c) e4[c * 32 + lane] = z;
        return;
    }

    // warp 0: load relu(x) as raw bits, 32 values per lane, coalesced
    unsigned pb[32];
    const float4* row = reinterpret_cast<const float4*>(emb + (size_t)t * D);
#pragma unroll
    for (int c = 0; c < 8; ++c) {
        float4 x = row[c * 32 + lane];
        pb[c * 4 + 0] = __float_as_uint(fmaxf(x.x, 0.f));
        pb[c * 4 + 1] = __float_as_uint(fmaxf(x.y, 0.f));
        pb[c * 4 + 2] = __float_as_uint(fmaxf(x.z, 0.f));
        pb[c * 4 + 3] = __float_as_uint(fmaxf(x.w, 0.f));
    }

    // 1-bit radix: max T with count(bits >= T) >= TOPK, early-exit on ==.
    unsigned thr = 0u;
#pragma unroll 1
    for (int b = 30; b >= 0; --b) {
        const unsigned cand = thr | (1u << b);
        int c = 0;
#pragma unroll
        for (int k = 0; k < 32; ++k) c += (pb[k] >= cand) ? 1 : 0;
        c = __reduce_add_sync(0xffffffffu, c);
        if (c >= TOPK) {
            thr = cand;
            if (c == TOPK) break;  // mask already exact
        }
    }

    float4* outp = reinterpret_cast<float4*>(g_sbuf + (size_t)t * D);
#pragma unroll
    for (int c = 0; c < 8; ++c) {
        float4 sv;
        sv.x = (pb[c * 4 + 0] >= thr) ? __uint_as_float(pb[c * 4 + 0]) : 0.f;
        sv.y = (pb[c * 4 + 1] >= thr) ? __uint_as_float(pb[c * 4 + 1]) : 0.f;
        sv.z = (pb[c * 4 + 2] >= thr) ? __uint_as_float(pb[c * 4 + 2]) : 0.f;
        sv.w = (pb[c * 4 + 3] >= thr) ? __uint_as_float(pb[c * 4 + 3]) : 0.f;
        outp[c * 32 + lane] = sv;
    }
}

// ---------------------------------------------------------------------------
// Kernel 2: the scan with fused expectation accumulation (proven engine).
//     v <- relu(DECAY*v + s_t[i]*s_t[j]*g_t),   g_t = 1 - c_t*INHIB
// Thread owns 4 rows x 4 cols; v register-resident across all 128 steps;
// snapshots stream out with __stcs. s_{t+1}[i]*v -> g_expect[t+1] via one
// red.global.v4 (block-uniform skip when all 4 s-rows are zero, ~81%).
// PDL: g_sh (input-only) staged BEFORE the grid-dependency sync.
// ---------------------------------------------------------------------------
__global__ void __launch_bounds__(256) scan_kernel(const float* __restrict__ con,
                                                  float* __restrict__ states) {
    const int tid = threadIdx.x;
    const int i0 = blockIdx.x * SCAN_R;
    const int j = tid * 4;

    __shared__ float4 si_sh[S];  // s_t[i0..i0+3] for all t
    __shared__ float g_sh[S];

    // Pre-sync work: depends only on kernel inputs, not on sparsify.
    if (tid < S) g_sh[tid] = 1.0f - con[tid] * INHIB;

    cudaGridDependencySynchronize();  // PDL: wait for sparsify completion

    if (tid < S)
        si_sh[tid] = *reinterpret_cast<const float4*>(g_sbuf + (size_t)tid * D + i0);
    __syncthreads();

    float4 v[SCAN_R];
#pragma unroll
    for (int r = 0; r < SCAN_R; ++r) v[r] = make_float4(0.f, 0.f, 0.f, 0.f);

    float4 sj = __ldg(reinterpret_cast<const float4*>(g_sbuf + j));  // s_t[j..j+3]
    for (int t = 0; t < S; ++t) {
        float4 sjn = sj;
        if (t + 1 < S)
            sjn = __ldg(reinterpret_cast<const float4*>(g_sbuf + (size_t)(t + 1) * D + j));
        const float g = g_sh[t];
        const float4 si = si_sh[t];
        const float a0 = si.x * g, a1 = si.y * g, a2 = si.z * g, a3 = si.w * g;
        float* o = states + (size_t)t * D * D + j;

        v[0].x = fmaxf(fmaf(a0, sj.x, DECAY * v[0].x), 0.f);
        v[0].y = fmaxf(fmaf(a0, sj.y, DECAY * v[0].y), 0.f);
        v[0].z = fmaxf(fmaf(a0, sj.z, DECAY * v[0].z), 0.f);
        v[0].w = fmaxf(fmaf(a0, sj.w, DECAY * v[0].w), 0.f);
        v[1].x = fmaxf(fmaf(a1, sj.x, DECAY * v[1].x), 0.f);
        v[1].y = fmaxf(fmaf(a1, sj.y, DECAY * v[1].y), 0.f);
        v[1].z = fmaxf(fmaf(a1, sj.z, DECAY * v[1].z), 0.f);
        v[1].w = fmaxf(fmaf(a1, sj.w, DECAY * v[1].w), 0.f);
        v[2].x = fmaxf(fmaf(a2, sj.x, DECAY * v[2].x), 0.f);
        v[2].y = fmaxf(fmaf(a2, sj.y, DECAY * v[2].y), 0.f);
        v[2].z = fmaxf(fmaf(a2, sj.z, DECAY * v[2].z), 0.f);
        v[2].w = fmaxf(fmaf(a2, sj.w, DECAY * v[2].w), 0.f);
        v[3].x = fmaxf(fmaf(a3, sj.x, DECAY * v[3].x), 0.f);
        v[3].y = fmaxf(fmaf(a3, sj.y, DECAY * v[3].y), 0.f);
        v[3].z = fmaxf(fmaf(a3, sj.z, DECAY * v[3].z), 0.f);
        v[3].w = fmaxf(fmaf(a3, sj.w, DECAY * v[3].w), 0.f);

        __stcs(reinterpret_cast<float4*>(o + (size_t)(i0 + 0) * D), v[0]);
        __stcs(reinterpret_cast<float4*>(o + (size_t)(i0 + 1) * D), v[1]);
        __stcs(reinterpret_cast<float4*>(o + (size_t)(i0 + 2) * D), v[2]);
        __stcs(reinterpret_cast<float4*>(o + (size_t)(i0 + 3) * D), v[3]);

        if (t + 1 < S) {
            const float4 sn = si_sh[t + 1];  // block-uniform
            if (sn.x != 0.f || sn.y != 0.f || sn.z != 0.f || sn.w != 0.f) {
                float4 cacc;
                cacc.x = sn.x * v[0].x + sn.y * v[1].x + sn.z * v[2].x + sn.w * v[3].x;
                cacc.y = sn.x * v[0].y + sn.y * v[1].y + sn.z * v[2].y + sn.w * v[3].y;
                cacc.z = sn.x * v[0].z + sn.y * v[1].z + sn.z * v[2].z + sn.w * v[3].z;
                cacc.w = sn.x * v[0].w + sn.y * v[1].w + sn.z * v[2].w + sn.w * v[3].w;
                red_add_v4(g_expect + (size_t)(t + 1) * D + j, cacc);
            }
        }
        sj = sjn;
    }
}

// ---------------------------------------------------------------------------
// Kernel 3: finalize. drift_t = ||s_t - expect_t|| (expect_0 = 0 => ||s_0||).
// All loads strictly AFTER the dependency sync: no read traffic may race the
// scan's saturated write stream (R9 lesson).
// ---------------------------------------------------------------------------
__global__ void __launch_bounds__(256) finalize_kernel(float* __restrict__ drifts) {
    cudaGridDependencySynchronize();  // PDL: wait for scan completion

    const int t = blockIdx.x;
    const int tid = threadIdx.x;
    const int lane = tid & 31, wid = tid >> 5;

    float4 s4 = reinterpret_cast<const float4*>(g_sbuf + (size_t)t * D)[tid];
    float4 e4 = reinterpret_cast<const float4*>(g_expect + (size_t)t * D)[tid];
    const float dx = s4.x - e4.x, dy = s4.y - e4.y;
    const float dz = s4.z - e4.z, dw = s4.w - e4.w;
    float sum = dx * dx + dy * dy + dz * dz + dw * dw;
#pragma unroll
    for (int o = 16; o > 0; o >>= 1) sum += __shfl_xor_sync(0xffffffffu, sum, o);

    __shared__ float ws[8];
    if (lane == 0) ws[wid] = sum;
    __syncthreads();
    if (tid == 0) {
        float tot = 0.f;
        for (int w = 0; w < 8; ++w) tot += ws[w];
        drifts[t] = sqrtf(tot);
    }
}

// ---------------------------------------------------------------------------
extern "C" void kernel_launch(void* const* d_in, const int* in_sizes, int n_in,
                              void* d_out, int out_size) {
    const float* emb;
    const float* con;
    if (in_sizes[0] == S) {
        con = (const float*)d_in[0];
        emb = (const float*)d_in[1];
    } else {
        emb = (const float*)d_in[0];
        con = (const float*)d_in[1];
    }
    float* out = (float*)d_out;
    float* drifts = out;      // [S]
    float* states = out + S;  // [S, D, D]

    sparsify_kernel<<<S, 64>>>(emb);

    cudaLaunchAttribute attr[1];
    attr[0].id = cudaLaunchAttributeProgrammaticStreamSerialization;
    attr[0].val.programmaticStreamSerializationAllowed = 1;

    {
        cudaLaunchConfig_t cfg = {};
        cfg.gridDim = dim3(D / SCAN_R);
        cfg.blockDim = dim3(256);
        cfg.dynamicSmemBytes = 0;
        cfg.stream = (cudaStream_t)0;
        cfg.attrs = attr;
        cfg.numAttrs = 1;
        cudaLaunchKernelEx(&cfg, scan_kernel, con, states);
    }
    {
        cudaLaunchConfig_t cfg = {};
        cfg.gridDim = dim3(S);
        cfg.blockDim = dim3(256);
        cfg.dynamicSmemBytes = 0;
        cfg.stream = (cudaStream_t)0;
        cfg.attrs = attr;
        cfg.numAttrs = 1;
        cudaLaunchKernelEx(&cfg, finalize_kernel, drifts);
    }
}

// round 11
// speedup vs baseline: 1.2131x; 1.0584x over previous
#include <cuda_runtime.h>
#include <math.h>

#define D 1024
#define S 128
#define DECAY 0.99f
#define INHIB 1.5f
#define TOPK 51
#define SCAN_R 8   // rows per thread
#define SCAN_T 128 // threads per block (block covers SCAN_T*4 = 512 columns)

// Scratch (static device globals — no allocation).
__device__ float g_sbuf[S * D];    // sparsified token vectors [S][D]
__device__ float g_expect[S * D];  // expectation_t[j] accumulated by scan reds

// Vector float4 global reduction (sm_90+): one REDG instead of four.
__device__ __forceinline__ void red_add_v4(float* p, float4 v) {
    asm volatile("red.global.add.v4.f32 [%0], {%1, %2, %3, %4};"
                 :: "l"(p), "f"(v.x), "f"(v.y), "f"(v.z), "f"(v.w)
                 : "memory");
}

// ---------------------------------------------------------------------------
// Kernel 1: sparsify. 128 blocks x 64 threads (one radix warp per SM).
// Warp 0: exact 1-bit radix top-k with early exit (mask-equivalent threshold).
// Warp 1: zero g_expect row bid.
// ---------------------------------------------------------------------------
__global__ void __launch_bounds__(64) sparsify_kernel(const float* __restrict__ emb) {
    const int t = blockIdx.x;
    const int lane = threadIdx.x & 31;

    if (threadIdx.x >= 32) {  // warp 1: zero g_expect row t
        float4 z = make_float4(0.f, 0.f, 0.f, 0.f);
        float4* e4 = reinterpret_cast<float4*>(g_expect + (size_t)t * D);
#pragma unroll
        for (int c = 0; c < 8; ++c) e4[c * 32 + lane] = z;
        return;
    }

    unsigned pb[32];
    const float4* row = reinterpret_cast<const float4*>(emb + (size_t)t * D);
#pragma unroll
    for (int c = 0; c < 8; ++c) {
        float4 x = row[c * 32 + lane];
        pb[c * 4 + 0] = __float_as_uint(fmaxf(x.x, 0.f));
        pb[c * 4 + 1] = __float_as_uint(fmaxf(x.y, 0.f));
        pb[c * 4 + 2] = __float_as_uint(fmaxf(x.z, 0.f));
        pb[c * 4 + 3] = __float_as_uint(fmaxf(x.w, 0.f));
    }

    // 1-bit radix: max T with count(bits >= T) >= TOPK, early-exit on ==.
    unsigned thr = 0u;
#pragma unroll 1
    for (int b = 30; b >= 0; --b) {
        const unsigned cand = thr | (1u << b);
        int c = 0;
#pragma unroll
        for (int k = 0; k < 32; ++k) c += (pb[k] >= cand) ? 1 : 0;
        c = __reduce_add_sync(0xffffffffu, c);
        if (c >= TOPK) {
            thr = cand;
            if (c == TOPK) break;  // mask already exact
        }
    }

    float4* outp = reinterpret_cast<float4*>(g_sbuf + (size_t)t * D);
#pragma unroll
    for (int c = 0; c < 8; ++c) {
        float4 sv;
        sv.x = (pb[c * 4 + 0] >= thr) ? __uint_as_float(pb[c * 4 + 0]) : 0.f;
        sv.y = (pb[c * 4 + 1] >= thr) ? __uint_as_float(pb[c * 4 + 1]) : 0.f;
        sv.z = (pb[c * 4 + 2] >= thr) ? __uint_as_float(pb[c * 4 + 2]) : 0.f;
        sv.w = (pb[c * 4 + 3] >= thr) ? __uint_as_float(pb[c * 4 + 3]) : 0.f;
        outp[c * 32 + lane] = sv;
    }
}

// ---------------------------------------------------------------------------
// Kernel 2: the scan, retiled 8 rows x 4 cols per thread, 128-thread blocks.
// Block covers 512 columns -> per-step row read footprint halves (128->64 MB
// total L2 reads), cutting LTS contention with the saturated store stream.
// Grid: 128 row-groups x 2 col-groups = 256 blocks (all SMs busy).
//     v <- relu(DECAY*v + s_t[i]*s_t[j]*g_t),   g_t = 1 - c_t*INHIB
// v register-resident (8 float4); snapshots stream out via __stcs.
// s_{t+1}[i].v -> g_expect[t+1] via one red.global.v4 (guarded on the 8
// block-uniform s-row values, fires ~34% of steps).
// ---------------------------------------------------------------------------
__global__ void __launch_bounds__(SCAN_T) scan_kernel(const float* __restrict__ con,
                                                     float* __restrict__ states) {
    const int tid = threadIdx.x;
    const int i0 = (blockIdx.x >> 1) * SCAN_R;           // 8-row group
    const int j = (blockIdx.x & 1) * (SCAN_T * 4) + tid * 4;  // column

    __shared__ float4 si_a[S];   // s_t[i0..i0+3]
    __shared__ float4 si_b[S];   // s_t[i0+4..i0+7]
    __shared__ float g_sh[S];

    // Pre-sync work: depends only on kernel inputs, not on sparsify.
    g_sh[tid] = 1.0f - con[tid] * INHIB;   // SCAN_T == S == 128

    cudaGridDependencySynchronize();  // PDL: wait for sparsify completion

    {
        const float4* p = reinterpret_cast<const float4*>(g_sbuf + (size_t)tid * D + i0);
        si_a[tid] = p[0];
        si_b[tid] = p[1];
    }
    __syncthreads();

    float4 v[SCAN_R];
#pragma unroll
    for (int r = 0; r < SCAN_R; ++r) v[r] = make_float4(0.f, 0.f, 0.f, 0.f);

    float4 sj = __ldg(reinterpret_cast<const float4*>(g_sbuf + j));  // s_t[j..j+3]
#pragma unroll 1
    for (int t = 0; t < S; ++t) {
        float4 sjn = sj;
        if (t + 1 < S)
            sjn = __ldg(reinterpret_cast<const float4*>(g_sbuf + (size_t)(t + 1) * D + j));
        const float g = g_sh[t];
        const float4 sia = si_a[t];
        const float4 sib = si_b[t];
        float a[SCAN_R];
        a[0] = sia.x * g; a[1] = sia.y * g; a[2] = sia.z * g; a[3] = sia.w * g;
        a[4] = sib.x * g; a[5] = sib.y * g; a[6] = sib.z * g; a[7] = sib.w * g;
        float* o = states + (size_t)t * D * D + j;

#pragma unroll
        for (int r = 0; r < SCAN_R; ++r) {
            v[r].x = fmaxf(fmaf(a[r], sj.x, DECAY * v[r].x), 0.f);
            v[r].y = fmaxf(fmaf(a[r], sj.y, DECAY * v[r].y), 0.f);
            v[r].z = fmaxf(fmaf(a[r], sj.z, DECAY * v[r].z), 0.f);
            v[r].w = fmaxf(fmaf(a[r], sj.w, DECAY * v[r].w), 0.f);
            __stcs(reinterpret_cast<float4*>(o + (size_t)(i0 + r) * D), v[r]);
        }

        if (t + 1 < S) {
            const float4 sna = si_a[t + 1];   // block-uniform
            const float4 snb = si_b[t + 1];
            const bool any =
                sna.x != 0.f || sna.y != 0.f || sna.z != 0.f || sna.w != 0.f ||
                snb.x != 0.f || snb.y != 0.f || snb.z != 0.f || snb.w != 0.f;
            if (any) {
                float sn[SCAN_R] = {sna.x, sna.y, sna.z, sna.w,
                                    snb.x, snb.y, snb.z, snb.w};
                float4 cacc = make_float4(0.f, 0.f, 0.f, 0.f);
#pragma unroll
                for (int r = 0; r < SCAN_R; ++r) {
                    cacc.x = fmaf(sn[r], v[r].x, cacc.x);
                    cacc.y = fmaf(sn[r], v[r].y, cacc.y);
                    cacc.z = fmaf(sn[r], v[r].z, cacc.z);
                    cacc.w = fmaf(sn[r], v[r].w, cacc.w);
                }
                red_add_v4(g_expect + (size_t)(t + 1) * D + j, cacc);
            }
        }
        sj = sjn;
    }
}

// ---------------------------------------------------------------------------
// Kernel 3: finalize. drift_t = ||s_t - expect_t|| (expect_0 = 0 => ||s_0||).
// All loads strictly AFTER the dependency sync (R9 lesson).
// ---------------------------------------------------------------------------
__global__ void __launch_bounds__(256) finalize_kernel(float* __restrict__ drifts) {
    cudaGridDependencySynchronize();  // PDL: wait for scan completion

    const int t = blockIdx.x;
    const int tid = threadIdx.x;
    const int lane = tid & 31, wid = tid >> 5;

    float4 s4 = reinterpret_cast<const float4*>(g_sbuf + (size_t)t * D)[tid];
    float4 e4 = reinterpret_cast<const float4*>(g_expect + (size_t)t * D)[tid];
    const float dx = s4.x - e4.x, dy = s4.y - e4.y;
    const float dz = s4.z - e4.z, dw = s4.w - e4.w;
    float sum = dx * dx + dy * dy + dz * dz + dw * dw;
#pragma unroll
    for (int o = 16; o > 0; o >>= 1) sum += __shfl_xor_sync(0xffffffffu, sum, o);

    __shared__ float ws[8];
    if (lane == 0) ws[wid] = sum;
    __syncthreads();
    if (tid == 0) {
        float tot = 0.f;
        for (int w = 0; w < 8; ++w) tot += ws[w];
        drifts[t] = sqrtf(tot);
    }
}

// ---------------------------------------------------------------------------
extern "C" void kernel_launch(void* const* d_in, const int* in_sizes, int n_in,
                              void* d_out, int out_size) {
    const float* emb;
    const float* con;
    if (in_sizes[0] == S) {
        con = (const float*)d_in[0];
        emb = (const float*)d_in[1];
    } else {
        emb = (const float*)d_in[0];
        con = (const float*)d_in[1];
    }
    float* out = (float*)d_out;
    float* drifts = out;      // [S]
    float* states = out + S;  // [S, D, D]

    sparsify_kernel<<<S, 64>>>(emb);

    cudaLaunchAttribute attr[1];
    attr[0].id = cudaLaunchAttributeProgrammaticStreamSerialization;
    attr[0].val.programmaticStreamSerializationAllowed = 1;

    {
        cudaLaunchConfig_t cfg = {};
        cfg.gridDim = dim3((D / SCAN_R) * 2);   // 256 blocks
        cfg.blockDim = dim3(SCAN_T);
        cfg.dynamicSmemBytes = 0;
        cfg.stream = (cudaStream_t)0;
        cfg.attrs = attr;
        cfg.numAttrs = 1;
        cudaLaunchKernelEx(&cfg, scan_kernel, con, states);
    }
    {
        cudaLaunchConfig_t cfg = {};
        cfg.gridDim = dim3(S);
        cfg.blockDim = dim3(256);
        cfg.dynamicSmemBytes = 0;
        cfg.stream = (cudaStream_t)0;
        cfg.attrs = attr;
        cfg.numAttrs = 1;
        cudaLaunchKernelEx(&cfg, finalize_kernel, drifts);
    }
}